// round 4
// baseline (speedup 1.0000x reference)
#include <cuda_runtime.h>
#include <math.h>

#define BB 2
#define SS 2048
#define EE 1024
#define HH 16
#define DD 64
#define MAXREL 512

// ---------------- device scratch (allocation-free: device globals, 64MB) ----
__device__ float g_Qh[BB * HH * SS * DD];   // [B,H,S,D]
__device__ float g_Kh[BB * HH * SS * DD];
__device__ float g_Vh[BB * HH * SS * DD];
__device__ float g_Oh[BB * HH * SS * DD];

#define QROW(i) (((i) < 4) ? (ty * 4 + (i)) : (64 + ty * 4 + (i) - 4))

// ============================================================================
// Projection GEMM: C[128x128] tile, 256 threads, 8x8 micro, k-step 32.
// Swizzled smem: T[row*32 + (c4 ^ ((row>>2)&7))*4], 32 KB static total.
// ============================================================================

// ---------------- fused QKV projection: X @ W^T + b -> [B,H,S,D] ------------
// grid: (EE/128, (BB*SS)/128, 3), block: 256
__global__ __launch_bounds__(256) void proj_qkv_kernel(
    const float* __restrict__ Xq, const float* __restrict__ Xk, const float* __restrict__ Xv,
    const float* __restrict__ Wq, const float* __restrict__ bq,
    const float* __restrict__ Wk, const float* __restrict__ bk,
    const float* __restrict__ Wv, const float* __restrict__ bv)
{
    const int z = blockIdx.z;
    const float* X    = (z == 0) ? Xq : (z == 1) ? Xk : Xv;
    const float* W    = (z == 0) ? Wq : (z == 1) ? Wk : Wv;
    const float* bias = (z == 0) ? bq : (z == 1) ? bk : bv;
    float* dst        = (z == 0) ? g_Qh : (z == 1) ? g_Kh : g_Vh;

    __shared__ float SA[128 * 32];
    __shared__ float SB[128 * 32];

    const int m0 = blockIdx.y * 128;
    const int n0 = blockIdx.x * 128;
    const int t  = threadIdx.x;
    const int ty = t >> 4, tx = t & 15;
    const int lrow = t >> 3;   // 0..31
    const int lc4  = t & 7;    // 0..7

    float acc[8][8];
#pragma unroll
    for (int i = 0; i < 8; i++)
#pragma unroll
        for (int j = 0; j < 8; j++) acc[i][j] = 0.f;

    for (int k0 = 0; k0 < EE; k0 += 32) {
        float4 ra[4], rb[4];
#pragma unroll
        for (int i = 0; i < 4; i++) {
            int row = lrow + i * 32;
            ra[i] = *(const float4*)&X[(size_t)(m0 + row) * EE + k0 + lc4 * 4];
            rb[i] = *(const float4*)&W[(size_t)(n0 + row) * EE + k0 + lc4 * 4];
        }
        __syncthreads();
#pragma unroll
        for (int i = 0; i < 4; i++) {
            int row = lrow + i * 32;
            int sw = (lc4 ^ ((row >> 2) & 7)) * 4;
            *(float4*)&SA[row * 32 + sw] = ra[i];
            *(float4*)&SB[row * 32 + sw] = rb[i];
        }
        __syncthreads();
#pragma unroll 4
        for (int kk = 0; kk < 8; kk++) {
            float4 a[8], b[8];
            int swA = (kk ^ (ty & 7)) * 4;
            int swB = (kk ^ (tx & 7)) * 4;
#pragma unroll
            for (int i = 0; i < 4; i++) {
                a[i]     = *(const float4*)&SA[(ty * 4 + i) * 32 + swA];
                a[i + 4] = *(const float4*)&SA[(64 + ty * 4 + i) * 32 + swA];
                b[i]     = *(const float4*)&SB[(tx * 4 + i) * 32 + swB];
                b[i + 4] = *(const float4*)&SB[(64 + tx * 4 + i) * 32 + swB];
            }
#pragma unroll
            for (int i = 0; i < 8; i++)
#pragma unroll
                for (int j = 0; j < 8; j++)
                    acc[i][j] += a[i].x * b[j].x + a[i].y * b[j].y +
                                 a[i].z * b[j].z + a[i].w * b[j].w;
        }
    }

#pragma unroll
    for (int i = 0; i < 8; i++) {
        int m = m0 + QROW(i);
        int b_ = m >> 11, s_ = m & 2047;
#pragma unroll
        for (int jj = 0; jj < 2; jj++) {
            int n = n0 + jj * 64 + tx * 4;
            int h = n >> 6, d = n & 63;
            float4 o;
            o.x = acc[i][jj * 4 + 0] + bias[n + 0];
            o.y = acc[i][jj * 4 + 1] + bias[n + 1];
            o.z = acc[i][jj * 4 + 2] + bias[n + 2];
            o.w = acc[i][jj * 4 + 3] + bias[n + 3];
            *(float4*)&dst[(((size_t)b_ * HH + h) * SS + s_) * DD + d] = o;
        }
    }
}

// ---------------- output projection: Oh(reshaped) @ Wo^T + bo ---------------
// grid: (EE/128, (BB*SS)/128), block 256
__global__ __launch_bounds__(256) void out_proj_kernel(
    const float* __restrict__ Wo, const float* __restrict__ bo, float* __restrict__ out)
{
    __shared__ float SA[128 * 32];
    __shared__ float SB[128 * 32];

    const int m0 = blockIdx.y * 128;
    const int n0 = blockIdx.x * 128;
    const int t  = threadIdx.x;
    const int ty = t >> 4, tx = t & 15;
    const int lrow = t >> 3;
    const int lc4  = t & 7;

    float acc[8][8];
#pragma unroll
    for (int i = 0; i < 8; i++)
#pragma unroll
        for (int j = 0; j < 8; j++) acc[i][j] = 0.f;

    for (int k0 = 0; k0 < EE; k0 += 32) {
        float4 ra[4], rb[4];
        int kc = k0 + lc4 * 4;
        int hh = kc >> 6, dd = kc & 63;
#pragma unroll
        for (int i = 0; i < 4; i++) {
            int row = lrow + i * 32;
            int m = m0 + row;
            int b_ = m >> 11, s_ = m & 2047;
            ra[i] = *(const float4*)&g_Oh[(((size_t)b_ * HH + hh) * SS + s_) * DD + dd];
            rb[i] = *(const float4*)&Wo[(size_t)(n0 + row) * EE + kc];
        }
        __syncthreads();
#pragma unroll
        for (int i = 0; i < 4; i++) {
            int row = lrow + i * 32;
            int sw = (lc4 ^ ((row >> 2) & 7)) * 4;
            *(float4*)&SA[row * 32 + sw] = ra[i];
            *(float4*)&SB[row * 32 + sw] = rb[i];
        }
        __syncthreads();
#pragma unroll 4
        for (int kk = 0; kk < 8; kk++) {
            float4 a[8], b[8];
            int swA = (kk ^ (ty & 7)) * 4;
            int swB = (kk ^ (tx & 7)) * 4;
#pragma unroll
            for (int i = 0; i < 4; i++) {
                a[i]     = *(const float4*)&SA[(ty * 4 + i) * 32 + swA];
                a[i + 4] = *(const float4*)&SA[(64 + ty * 4 + i) * 32 + swA];
                b[i]     = *(const float4*)&SB[(tx * 4 + i) * 32 + swB];
                b[i + 4] = *(const float4*)&SB[(64 + tx * 4 + i) * 32 + swB];
            }
#pragma unroll
            for (int i = 0; i < 8; i++)
#pragma unroll
                for (int j = 0; j < 8; j++)
                    acc[i][j] += a[i].x * b[j].x + a[i].y * b[j].y +
                                 a[i].z * b[j].z + a[i].w * b[j].w;
        }
    }

#pragma unroll
    for (int i = 0; i < 8; i++) {
        int mm = m0 + QROW(i);
#pragma unroll
        for (int jj = 0; jj < 2; jj++) {
            int n = n0 + jj * 64 + tx * 4;
            float4 o;
            o.x = acc[i][jj * 4 + 0] + bo[n + 0];
            o.y = acc[i][jj * 4 + 1] + bo[n + 1];
            o.z = acc[i][jj * 4 + 2] + bo[n + 2];
            o.w = acc[i][jj * 4 + 3] + bo[n + 3];
            *(float4*)&out[(size_t)mm * EE + n] = o;
        }
    }
}

// ============================================================================
// Attention spill kernel: q-tile 128, k-tile 64, 8x4 micro, two-pass,
// 48 KB STATIC smem (no attributes, no dynamic smem):
//   pool[12288] floats:  pass1: SQ=pool[0,8192), SK=pool[8192,12288)
//                        pass2: SP=pool[0,8192), SVt=pool[8192,12288)
// Rel-bias handled in registers: 14 values per thread per k-tile.
// grid: (SS/128, BB*HH), block 256
// ============================================================================
__global__ __launch_bounds__(256) void attn_spill_kernel(
    const float* __restrict__ rtab, float* __restrict__ attn)
{
    __shared__ float pool[12288];
    float* SQ  = pool;           // [128][64] swizzled
    float* SK  = pool + 8192;    // [64][64]  swizzled
    float* SP  = pool;           // [128][64] swizzled (pass 2)
    float* SVt = pool + 8192;    // [64(d)][64(k)] swizzled (pass 2)

    const int q0 = blockIdx.x * 128;
    const int bh = blockIdx.y;
    const int h  = bh & (HH - 1);
    const int t  = threadIdx.x;
    const int ty = t >> 4, tx = t & 15;
    const float scale = 0.125f;  // 1/sqrt(64)

    const float* Qb = g_Qh + (size_t)bh * SS * DD;
    const float* Kb = g_Kh + (size_t)bh * SS * DD;
    const float* Vb = g_Vh + (size_t)bh * SS * DD;
    float* attn_bh  = attn + (size_t)bh * SS * SS;

    // load Q tile [128][64] swizzled (ordered by first in-loop sync)
#pragma unroll
    for (int i = 0; i < 8; i++) {
        int idx = t + i * 256;
        int row = idx >> 4, c4 = idx & 15;
        float4 v = *(const float4*)&Qb[(size_t)(q0 + row) * DD + c4 * 4];
        *(float4*)&SQ[row * 64 + (c4 ^ ((row >> 2) & 7)) * 4] = v;
    }

    const int ntiles = 2 * (blockIdx.x + 1);  // 64-wide k tiles
    float m[8], l[8];
#pragma unroll
    for (int i = 0; i < 8; i++) { m[i] = -INFINITY; l[i] = 0.f; }

    // ---------------- PASS 1: scores -> gmem (raw) + online (m, l) ----------
    for (int kt = 0; kt < ntiles; kt++) {
        const int k0 = kt * 64;
        // K tile [64][64]: 4 float4 per thread
        float4 rk[4];
#pragma unroll
        for (int i = 0; i < 4; i++) {
            int idx = t + i * 256;
            int row = idx >> 4, c4 = idx & 15;
            rk[i] = *(const float4*)&Kb[(size_t)(k0 + row) * DD + c4 * 4];
        }
        // rel bias registers: rel = (q0-k0) + 4(ty-tx) + (dd-3) + 64e
        float breg[2][7];
#pragma unroll
        for (int e = 0; e < 2; e++)
#pragma unroll
            for (int dd = 0; dd < 7; dd++) {
                int rel = (q0 - k0) + 4 * (ty - tx) + (dd - 3) + 64 * e;
                rel = rel < -MAXREL ? -MAXREL : (rel > MAXREL ? MAXREL : rel);
                breg[e][dd] = rtab[(rel + MAXREL) * HH + h];
            }
        __syncthreads();
#pragma unroll
        for (int i = 0; i < 4; i++) {
            int idx = t + i * 256;
            int row = idx >> 4, c4 = idx & 15;
            *(float4*)&SK[row * 64 + (c4 ^ ((row >> 2) & 7)) * 4] = rk[i];
        }
        __syncthreads();

        float s[8][4];
#pragma unroll
        for (int i = 0; i < 8; i++)
#pragma unroll
            for (int j = 0; j < 4; j++) s[i][j] = 0.f;

#pragma unroll 4
        for (int d4 = 0; d4 < 16; d4++) {
            float4 a[8], b[4];
            int swA = (d4 ^ (ty & 7)) * 4;
            int swB = (d4 ^ (tx & 7)) * 4;
#pragma unroll
            for (int i = 0; i < 4; i++) {
                a[i]     = *(const float4*)&SQ[(ty * 4 + i) * 64 + swA];
                a[i + 4] = *(const float4*)&SQ[(64 + ty * 4 + i) * 64 + swA];
                b[i]     = *(const float4*)&SK[(tx * 4 + i) * 64 + swB];
            }
#pragma unroll
            for (int i = 0; i < 8; i++)
#pragma unroll
                for (int j = 0; j < 4; j++)
                    s[i][j] += a[i].x * b[j].x + a[i].y * b[j].y +
                               a[i].z * b[j].z + a[i].w * b[j].w;
        }

#pragma unroll
        for (int i = 0; i < 8; i++) {
            int qr = QROW(i);
            int qi = q0 + qr;
#pragma unroll
            for (int j = 0; j < 4; j++) {
                int kc = tx * 4 + j;
                float v = s[i][j] * scale + breg[i >> 2][(i & 3) - j + 3];
                s[i][j] = ((k0 + kc) > qi) ? -INFINITY : v;
            }
            *(float4*)&attn_bh[(size_t)qi * SS + k0 + tx * 4] =
                make_float4(s[i][0], s[i][1], s[i][2], s[i][3]);

            float rm = fmaxf(fmaxf(s[i][0], s[i][1]), fmaxf(s[i][2], s[i][3]));
#pragma unroll
            for (int off = 8; off; off >>= 1)
                rm = fmaxf(rm, __shfl_xor_sync(0xffffffffu, rm, off));
            float mn = fmaxf(m[i], rm);
            float ps = __expf(s[i][0] - mn) + __expf(s[i][1] - mn) +
                       __expf(s[i][2] - mn) + __expf(s[i][3] - mn);
#pragma unroll
            for (int off = 8; off; off >>= 1)
                ps += __shfl_xor_sync(0xffffffffu, ps, off);
            l[i] = l[i] * __expf(m[i] - mn) + ps;
            m[i] = mn;
        }
    }

    float invl[8];
#pragma unroll
    for (int i = 0; i < 8; i++) invl[i] = 1.f / l[i];

    float o[8][4];
#pragma unroll
    for (int i = 0; i < 8; i++)
#pragma unroll
        for (int j = 0; j < 4; j++) o[i][j] = 0.f;

    // ---------------- PASS 2: p = exp(s-m)/l -> attn, O += P @ V -------------
    const int kb4 = t & 15;      // k-group (4 rows) for V transpose
    const int c4g = t >> 4;      // d-group (float4)

    for (int kt = 0; kt < ntiles; kt++) {
        const int k0 = kt * 64;
        // V transpose in registers: 4x4 block per thread
        float4 vr[4];
#pragma unroll
        for (int r = 0; r < 4; r++)
            vr[r] = *(const float4*)&Vb[(size_t)(k0 + kb4 * 4 + r) * DD + c4g * 4];
        float4 tv[4];
        tv[0] = make_float4(vr[0].x, vr[1].x, vr[2].x, vr[3].x);
        tv[1] = make_float4(vr[0].y, vr[1].y, vr[2].y, vr[3].y);
        tv[2] = make_float4(vr[0].z, vr[1].z, vr[2].z, vr[3].z);
        tv[3] = make_float4(vr[0].w, vr[1].w, vr[2].w, vr[3].w);

        // read raw scores, exp+normalize
        float4 p[8];
#pragma unroll
        for (int i = 0; i < 8; i++) {
            int qi = q0 + QROW(i);
            float4 sv = *(const float4*)&attn_bh[(size_t)qi * SS + k0 + tx * 4];
            p[i].x = __expf(sv.x - m[i]) * invl[i];
            p[i].y = __expf(sv.y - m[i]) * invl[i];
            p[i].z = __expf(sv.z - m[i]) * invl[i];
            p[i].w = __expf(sv.w - m[i]) * invl[i];
        }
        __syncthreads();   // prior tile's SP/SVt reads (or pass1 SQ reads) done
#pragma unroll
        for (int w = 0; w < 4; w++) {
            int d = c4g * 4 + w;
            *(float4*)&SVt[d * 64 + (kb4 ^ ((d >> 2) & 7)) * 4] = tv[w];
        }
#pragma unroll
        for (int i = 0; i < 8; i++) {
            int qr = QROW(i);
            int qi = q0 + qr;
            *(float4*)&attn_bh[(size_t)qi * SS + k0 + tx * 4] = p[i];
            *(float4*)&SP[qr * 64 + (tx ^ ((qr >> 2) & 7)) * 4] = p[i];
        }
        __syncthreads();

#pragma unroll 4
        for (int k4 = 0; k4 < 16; k4++) {
            float4 a[8], b[4];
            int swB = (k4 ^ (tx & 7)) * 4;
#pragma unroll
            for (int i = 0; i < 4; i++) {
                int swA0 = (k4 ^ (ty & 7)) * 4;
                a[i]     = *(const float4*)&SP[(ty * 4 + i) * 64 + swA0];
                a[i + 4] = *(const float4*)&SP[(64 + ty * 4 + i) * 64 + swA0];
                b[i]     = *(const float4*)&SVt[(tx * 4 + i) * 64 + swB];
            }
#pragma unroll
            for (int i = 0; i < 8; i++)
#pragma unroll
                for (int j = 0; j < 4; j++)
                    o[i][j] += a[i].x * b[j].x + a[i].y * b[j].y +
                               a[i].z * b[j].z + a[i].w * b[j].w;
        }
    }

    // zero-fill strictly-causal-masked region [q0+128, SS)
    const float4 z4 = make_float4(0.f, 0.f, 0.f, 0.f);
    for (int kt = blockIdx.x + 1; kt < SS / 128; kt++) {
        const int k0 = kt * 128;
#pragma unroll
        for (int i = 0; i < 16; i++) {
            int idx = t + i * 256;
            int row = idx >> 5, c4 = idx & 31;
            *(float4*)&attn_bh[(size_t)(q0 + row) * SS + k0 + c4 * 4] = z4;
        }
    }

    // write O heads (cols tx*4..tx*4+3 of 64)
#pragma unroll
    for (int i = 0; i < 8; i++) {
        int qr = QROW(i);
        *(float4*)&g_Oh[((size_t)bh * SS + q0 + qr) * DD + tx * 4] =
            make_float4(o[i][0], o[i][1], o[i][2], o[i][3]);
    }
}

// ---------------- attention, flash variant (fallback, out-only) -------------
// grid: (SS/64, BB*HH), block 256
__global__ __launch_bounds__(256) void attn_flash_kernel(const float* __restrict__ rtab)
{
    __shared__ float SA[64][68];
    __shared__ float SB[64][68];
    __shared__ float bias_f[128];

    const int q0 = blockIdx.x * 64;
    const int bh = blockIdx.y;
    const int h  = bh & (HH - 1);
    const int t  = threadIdx.x;
    const int ty = t >> 4, tx = t & 15;
    const float scale = 0.125f;

    const float* Qb = g_Qh + (size_t)bh * SS * DD;
    const float* Kb = g_Kh + (size_t)bh * SS * DD;
    const float* Vb = g_Vh + (size_t)bh * SS * DD;

    const int ntiles = (q0 >> 6) + 1;
    float m[4], l[4], o[4][4];
#pragma unroll
    for (int i = 0; i < 4; i++) {
        m[i] = -INFINITY; l[i] = 0.f;
#pragma unroll
        for (int j = 0; j < 4; j++) o[i][j] = 0.f;
    }

    for (int kt = 0; kt < ntiles; kt++) {
        const int k0 = kt * 64;
        __syncthreads();
#pragma unroll
        for (int i = 0; i < 4; i++) {
            int e = t + i * 256;
            int row = e >> 4, c4 = e & 15;
            *(float4*)&SA[row][c4 * 4] = *(const float4*)&Qb[(size_t)(q0 + row) * DD + c4 * 4];
            *(float4*)&SB[row][c4 * 4] = *(const float4*)&Kb[(size_t)(k0 + row) * DD + c4 * 4];
        }
        if (t < 127) {
            int rel = q0 - k0 - 63 + t;
            rel = rel < -MAXREL ? -MAXREL : (rel > MAXREL ? MAXREL : rel);
            bias_f[t] = rtab[(rel + MAXREL) * HH + h];
        }
        __syncthreads();

        float s[4][4];
#pragma unroll
        for (int i = 0; i < 4; i++)
#pragma unroll
            for (int j = 0; j < 4; j++) s[i][j] = 0.f;
#pragma unroll
        for (int d4 = 0; d4 < 16; d4++) {
            float4 a[4], b[4];
#pragma unroll
            for (int i = 0; i < 4; i++) a[i] = *(const float4*)&SA[ty * 4 + i][d4 * 4];
#pragma unroll
            for (int j = 0; j < 4; j++) b[j] = *(const float4*)&SB[tx * 4 + j][d4 * 4];
#pragma unroll
            for (int i = 0; i < 4; i++)
#pragma unroll
                for (int j = 0; j < 4; j++)
                    s[i][j] += a[i].x * b[j].x + a[i].y * b[j].y +
                               a[i].z * b[j].z + a[i].w * b[j].w;
        }

#pragma unroll
        for (int i = 0; i < 4; i++) {
            int qi = q0 + ty * 4 + i;
#pragma unroll
            for (int j = 0; j < 4; j++) {
                int kj = k0 + tx * 4 + j;
                float v = s[i][j] * scale + bias_f[(ty * 4 + i) - (tx * 4 + j) + 63];
                s[i][j] = (kj > qi) ? -INFINITY : v;
            }
        }

#pragma unroll
        for (int i = 0; i < 4; i++) {
            float rm = fmaxf(fmaxf(s[i][0], s[i][1]), fmaxf(s[i][2], s[i][3]));
#pragma unroll
            for (int off = 8; off; off >>= 1)
                rm = fmaxf(rm, __shfl_xor_sync(0xffffffffu, rm, off));
            float mn = fmaxf(m[i], rm);
            float corr = __expf(m[i] - mn);
            s[i][0] = __expf(s[i][0] - mn);
            s[i][1] = __expf(s[i][1] - mn);
            s[i][2] = __expf(s[i][2] - mn);
            s[i][3] = __expf(s[i][3] - mn);
            float ps = s[i][0] + s[i][1] + s[i][2] + s[i][3];
#pragma unroll
            for (int off = 8; off; off >>= 1)
                ps += __shfl_xor_sync(0xffffffffu, ps, off);
            l[i] = l[i] * corr + ps;
            m[i] = mn;
#pragma unroll
            for (int j = 0; j < 4; j++) o[i][j] *= corr;
        }

        __syncthreads();
#pragma unroll
        for (int i = 0; i < 4; i++)
            *(float4*)&SA[ty * 4 + i][tx * 4] = make_float4(s[i][0], s[i][1], s[i][2], s[i][3]);
#pragma unroll
        for (int i = 0; i < 4; i++) {
            int e = t + i * 256;
            int row = e >> 4, c4 = e & 15;
            *(float4*)&SB[row][c4 * 4] = *(const float4*)&Vb[(size_t)(k0 + row) * DD + c4 * 4];
        }
        __syncthreads();

#pragma unroll
        for (int k4 = 0; k4 < 16; k4++) {
            float4 a[4];
#pragma unroll
            for (int i = 0; i < 4; i++) a[i] = *(const float4*)&SA[ty * 4 + i][k4 * 4];
            float4 b0 = *(const float4*)&SB[k4 * 4 + 0][tx * 4];
            float4 b1 = *(const float4*)&SB[k4 * 4 + 1][tx * 4];
            float4 b2 = *(const float4*)&SB[k4 * 4 + 2][tx * 4];
            float4 b3 = *(const float4*)&SB[k4 * 4 + 3][tx * 4];
#pragma unroll
            for (int i = 0; i < 4; i++) {
                o[i][0] += a[i].x * b0.x + a[i].y * b1.x + a[i].z * b2.x + a[i].w * b3.x;
                o[i][1] += a[i].x * b0.y + a[i].y * b1.y + a[i].z * b2.y + a[i].w * b3.y;
                o[i][2] += a[i].x * b0.z + a[i].y * b1.z + a[i].z * b2.z + a[i].w * b3.z;
                o[i][3] += a[i].x * b0.w + a[i].y * b1.w + a[i].z * b2.w + a[i].w * b3.w;
            }
        }
    }

#pragma unroll
    for (int i = 0; i < 4; i++) {
        float inv = 1.f / l[i];
        *(float4*)&g_Oh[((size_t)bh * SS + q0 + ty * 4 + i) * DD + tx * 4] =
            make_float4(o[i][0] * inv, o[i][1] * inv, o[i][2] * inv, o[i][3] * inv);
    }
}

// ---------------- launch ----------------------------------------------------
extern "C" void kernel_launch(void* const* d_in, const int* in_sizes, int n_in,
                              void* d_out, int out_size)
{
    (void)in_sizes; (void)n_in;
    const float* query = (const float*)d_in[0];
    const float* key   = (const float*)d_in[1];
    const float* value = (const float*)d_in[2];
    const float* Wq    = (const float*)d_in[3];
    const float* bq    = (const float*)d_in[4];
    const float* Wk    = (const float*)d_in[5];
    const float* bk    = (const float*)d_in[6];
    const float* Wv    = (const float*)d_in[7];
    const float* bv    = (const float*)d_in[8];
    const float* Wo    = (const float*)d_in[9];
    const float* bo    = (const float*)d_in[10];
    const float* rtab  = (const float*)d_in[11];

    float* out = (float*)d_out;
    const size_t OUTN  = (size_t)BB * SS * EE;
    const size_t ATTNN = (size_t)BB * HH * SS * SS;

    proj_qkv_kernel<<<dim3(EE / 128, (BB * SS) / 128, 3), 256>>>(
        query, key, value, Wq, bq, Wk, bk, Wv, bv);

    if ((size_t)out_size >= OUTN + ATTNN) {
        float* attn = out + OUTN;
        attn_spill_kernel<<<dim3(SS / 128, BB * HH), 256>>>(rtab, attn);
    } else {
        attn_flash_kernel<<<dim3(SS / 64, BB * HH), 256>>>(rtab);
    }

    out_proj_kernel<<<dim3(EE / 128, (BB * SS) / 128), 256>>>(Wo, bo, out);
}